// round 9
// baseline (speedup 1.0000x reference)
#include <cuda_runtime.h>
#include <cstdint>

// Problem constants
#define BB 4
#define SS 4096
#define DF 1024
#define HH 16
#define HD 64
#define SK 1024          // SS / STRIDE
#define STRIDE 4
#define BQ 64            // q rows per CTA
#define BK 64            // k cols per block
#define NBLK (SK / BK)   // 16
#define NT 256
#define PAD 68           // floats per row (conflict-free for all frag patterns)
#define KSTG 17408       // bytes per 64x68 float stage

// Pre-rounded, stride-compacted K/V scratch: [b][t][DF], t = s/STRIDE
#define KVN (BB * SK * DF)   // 4,194,304 floats = 16 MB each
__device__ float g_kr[KVN];
__device__ float g_vr[KVN];

// smem layout: Q region (reused as reduction buffers) + 4 stages (K0,K1,V0,V1)
#define SM_Q   0                 // 64*68*4 = 17408
#define SM_ACC 0                 // epilogue: 4mg*32lane*33 floats = 16896
#define SM_RS  16896             // 128 floats
#define SM_S0  17408
#define SM_TOTAL (SM_S0 + 4*KSTG)   // 87040

__device__ __forceinline__ uint32_t smem_u32(const void* p) {
    uint32_t a;
    asm("{ .reg .u64 t; cvta.to.shared.u64 t, %1; cvt.u32.u64 %0, t; }" : "=r"(a) : "l"(p));
    return a;
}

#define CP_ASYNC16(sa, gp) \
    asm volatile("cp.async.cg.shared.global [%0], [%1], 16;" :: "r"(sa), "l"(gp) : "memory")
#define CP_COMMIT() asm volatile("cp.async.commit_group;" ::: "memory")
#define CP_WAIT(N)  asm volatile("cp.async.wait_group %0;" :: "n"(N) : "memory")

// D += A * B  (m16n8k8, tf32 in, f32 out)
__device__ __forceinline__ void mma_tf32(float c[4], const float a[4],
                                         float b0, float b1) {
    asm volatile(
        "mma.sync.aligned.m16n8k8.row.col.f32.tf32.tf32.f32 "
        "{%0,%1,%2,%3}, {%4,%5,%6,%7}, {%8,%9}, {%0,%1,%2,%3};"
        : "+f"(c[0]), "+f"(c[1]), "+f"(c[2]), "+f"(c[3])
        : "r"(__float_as_uint(a[0])), "r"(__float_as_uint(a[1])),
          "r"(__float_as_uint(a[2])), "r"(__float_as_uint(a[3])),
          "r"(__float_as_uint(b0)), "r"(__float_as_uint(b1)));
}

// round-to-nearest tf32
__device__ __forceinline__ float tf32_rn(float x) {
    return __uint_as_float((__float_as_uint(x) + 0x1000u) & 0xFFFFE000u);
}
__device__ __forceinline__ float ex2f(float x) {
    float y;
    asm("ex2.approx.f32 %0, %1;" : "=f"(y) : "f"(x));
    return y;
}

// ---- pre-kernel: round strided K/V rows to tf32 RN, compact into scratch ----
__global__ __launch_bounds__(NT)
void round_kv_kernel(const float* __restrict__ gk, const float* __restrict__ gv)
{
    int idx = blockIdx.x * NT + threadIdx.x;       // one float4 per thread
    int o = idx << 2;                               // float offset in compacted
    int b = o >> 20;                                // SK*DF = 2^20
    int rem = o & ((SK * DF) - 1);
    int t = rem >> 10, d = rem & (DF - 1);
    size_t src = ((size_t)b * SS + (size_t)t * STRIDE) * DF + d;
    float4 x = *(const float4*)&gk[src];
    x.x = tf32_rn(x.x); x.y = tf32_rn(x.y); x.z = tf32_rn(x.z); x.w = tf32_rn(x.w);
    *(float4*)&g_kr[o] = x;
    float4 y = *(const float4*)&gv[src];
    y.x = tf32_rn(y.x); y.y = tf32_rn(y.y); y.z = tf32_rn(y.z); y.w = tf32_rn(y.w);
    *(float4*)&g_vr[o] = y;
}

__global__ __launch_bounds__(NT, 2)
void attn_mma_kernel(const float* __restrict__ gq, float* __restrict__ out_a,
                     float* __restrict__ out_w)
{
    extern __shared__ char sm[];
    const uint32_t smb = smem_u32(sm);
    float* qs = (float*)(sm + SM_Q);

    const int tid = threadIdx.x, lane = tid & 31, warp = tid >> 5;
    const int gid = lane >> 2, gc = lane & 3;
    const int mg = warp >> 1, ng = warp & 1;
    const int b = blockIdx.z, h = blockIdx.y, q0 = blockIdx.x * BQ;
    const int r0 = mg * 16 + gid;

    const float* kbase = g_kr + (size_t)b * SK * DF + h * HD;
    const float* vbase = g_vr + (size_t)b * SK * DF + h * HD;

    const int lr = tid >> 4;              // rows lr, +16, +32, +48
    const int lc = (tid & 15) << 2;

    // ---- pre-issue K/V block 0 ----
    {
        #pragma unroll
        for (int i = 0; i < 4; i++) {
            int r = lr + i * 16;
            size_t goff = (size_t)r * DF + lc;
            CP_ASYNC16(smb + SM_S0 +            (uint32_t)(r * PAD + lc) * 4, kbase + goff);
            CP_ASYNC16(smb + SM_S0 + 2 * KSTG + (uint32_t)(r * PAD + lc) * 4, vbase + goff);
        }
        CP_COMMIT();
    }

    // ---- stage Q: scale by 0.125*log2(e), tf32 RN ----
    {
        const float SCL = 0.125f * 1.44269504088896341f;
        const float* qb = gq + ((size_t)(b * SS + q0)) * DF + h * HD;
        #pragma unroll
        for (int i = 0; i < 4; i++) {
            int idx = tid + i * NT;
            int r = idx >> 4, c4 = (idx & 15) << 2;
            float4 x = *(const float4*)&qb[(size_t)r * DF + c4];
            x.x = tf32_rn(x.x * SCL); x.y = tf32_rn(x.y * SCL);
            x.z = tf32_rn(x.z * SCL); x.w = tf32_rn(x.w * SCL);
            *(float4*)&qs[r * PAD + c4] = x;
        }
    }
    __syncthreads();

    // ---- Q fragments (permuted: slots {gc,gc+4} <-> d {8j+2gc, 8j+2gc+1}) ----
    float Qf[8][4];
    #pragma unroll
    for (int j = 0; j < 8; j++) {
        float2 fa = *(const float2*)&qs[r0 * PAD + j * 8 + 2 * gc];
        float2 fb = *(const float2*)&qs[(r0 + 8) * PAD + j * 8 + 2 * gc];
        Qf[j][0] = fa.x; Qf[j][1] = fb.x; Qf[j][2] = fa.y; Qf[j][3] = fb.y;
    }

    float Acc[8][4];
    #pragma unroll
    for (int t = 0; t < 8; t++) {
        Acc[t][0] = 0.f; Acc[t][1] = 0.f; Acc[t][2] = 0.f; Acc[t][3] = 0.f;
    }
    float rs0 = 0.f, rs1 = 0.f;

    for (int blk = 0; blk < NBLK; blk++) {
        CP_WAIT(0);
        __syncthreads();

        if (blk + 1 < NBLK) {
            const uint32_t ks_ = smb + SM_S0 + ((blk + 1) & 1) * KSTG;
            const uint32_t vs_ = ks_ + 2 * KSTG;
            #pragma unroll
            for (int i = 0; i < 4; i++) {
                int r = lr + i * 16;
                size_t goff = (size_t)((blk + 1) * BK + r) * DF + lc;
                CP_ASYNC16(ks_ + (uint32_t)(r * PAD + lc) * 4, kbase + goff);
                CP_ASYNC16(vs_ + (uint32_t)(r * PAD + lc) * 4, vbase + goff);
            }
            CP_COMMIT();
        }

        const float* kb = (const float*)(sm + SM_S0 + (blk & 1) * KSTG);
        const float* vb = kb + 2 * (KSTG / 4);

        // ---- S = Q * K^T  (pre-rounded K; float2 B-frags) ----
        const float* kbt0 = kb + (ng * 32 + gid) * PAD + 2 * gc;
        float S[4][4];
        #pragma unroll
        for (int t = 0; t < 4; t++) {
            S[t][0] = 0.f; S[t][1] = 0.f; S[t][2] = 0.f; S[t][3] = 0.f;
        }
        #pragma unroll
        for (int j = 0; j < 8; j++) {
            #pragma unroll
            for (int t = 0; t < 4; t++) {
                float2 bk = *(const float2*)&kbt0[t * 8 * PAD + j * 8];
                mma_tf32(S[t], Qf[j], bk.x, bk.y);
            }
        }

        // ---- p = 2^s, row-sum, unnormalized w -> gmem ----
        float* wr0 = out_w + (((size_t)(b * HH + h)) * SS + q0 + r0) * SK
                   + blk * BK + ng * 32;
        float* wr1 = wr0 + (size_t)8 * SK;
        #pragma unroll
        for (int t = 0; t < 4; t++) {
            float p0 = ex2f(S[t][0]), p1 = ex2f(S[t][1]);
            float p2 = ex2f(S[t][2]), p3 = ex2f(S[t][3]);
            rs0 += p0 + p1;
            rs1 += p2 + p3;
            int col = t * 8 + 2 * gc;
            *(float2*)&wr0[col] = make_float2(p0, p1);
            *(float2*)&wr1[col] = make_float2(p2, p3);
            S[t][0] = p0; S[t][1] = p1; S[t][2] = p2; S[t][3] = p3;
        }

        // ---- Acc += P * V  (pre-rounded V; direct C->A feed) ----
        // A-frag slots {c0,c2,c1,c3}; B rows 2gc, 2gc+1 within slice
        #pragma unroll
        for (int j = 0; j < 4; j++) {
            const float* vrow = vb + (ng * 32 + j * 8 + 2 * gc) * PAD + gid;
            float ap[4];
            ap[0] = S[j][0]; ap[1] = S[j][2];
            ap[2] = S[j][1]; ap[3] = S[j][3];
            #pragma unroll
            for (int t = 0; t < 8; t++) {
                mma_tf32(Acc[t], ap, vrow[t * 8], vrow[PAD + t * 8]);
            }
        }
    }

    // ---- combine k-slice partials ----
    rs0 += __shfl_xor_sync(0xFFFFFFFFu, rs0, 1);
    rs0 += __shfl_xor_sync(0xFFFFFFFFu, rs0, 2);
    rs1 += __shfl_xor_sync(0xFFFFFFFFu, rs1, 1);
    rs1 += __shfl_xor_sync(0xFFFFFFFFu, rs1, 2);

    __syncthreads();
    float* accbuf = (float*)(sm + SM_ACC);   // stride 33, scalar access
    float* rsb    = (float*)(sm + SM_RS);
    if (gc == 0) {
        rsb[ng * 64 + r0]     = rs0;
        rsb[ng * 64 + r0 + 8] = rs1;
    }
    if (ng == 1) {
        float* ab = accbuf + (mg * 32 + lane) * 33;
        #pragma unroll
        for (int t = 0; t < 8; t++) {
            ab[t * 4 + 0] = Acc[t][0];
            ab[t * 4 + 1] = Acc[t][1];
            ab[t * 4 + 2] = Acc[t][2];
            ab[t * 4 + 3] = Acc[t][3];
        }
    }
    __syncthreads();
    if (tid < 64) rsb[tid] = 1.0f / (rsb[tid] + rsb[64 + tid]);
    __syncthreads();

    if (ng == 0) {
        const float inv0 = rsb[r0], inv1 = rsb[r0 + 8];
        const float* pb = accbuf + (mg * 32 + lane) * 33;
        float* ar0 = out_a + ((size_t)(b * SS + q0 + r0)) * DF + h * HD;
        float* ar1 = ar0 + (size_t)8 * DF;
        #pragma unroll
        for (int t = 0; t < 8; t++) {
            float o0 = pb[t * 4 + 0], o1 = pb[t * 4 + 1];
            float o2 = pb[t * 4 + 2], o3 = pb[t * 4 + 3];
            int col = t * 8 + 2 * gc;
            *(float2*)&ar0[col] = make_float2((Acc[t][0] + o0) * inv0,
                                              (Acc[t][1] + o1) * inv0);
            *(float2*)&ar1[col] = make_float2((Acc[t][2] + o2) * inv1,
                                              (Acc[t][3] + o3) * inv1);
        }
    }

    // ---- w: rescale in place (L2-resident slab) ----
    {
        float* wslab = out_w + (((size_t)(b * HH + h)) * SS + q0) * SK;
        #pragma unroll 4
        for (int idx = tid; idx < BQ * 256; idx += NT) {
            int r = idx >> 8, c4 = (idx & 255) << 2;
            float il = rsb[r];
            float4 t = *(float4*)&wslab[(size_t)r * SK + c4];
            t.x *= il; t.y *= il; t.z *= il; t.w *= il;
            *(float4*)&wslab[(size_t)r * SK + c4] = t;
        }
    }
}

extern "C" void kernel_launch(void* const* d_in, const int* in_sizes, int n_in,
                              void* d_out, int out_size)
{
    (void)in_sizes; (void)n_in; (void)out_size;
    const float* q = (const float*)d_in[0];
    const float* k = (const float*)d_in[1];
    const float* v = (const float*)d_in[2];

    float* out_a = (float*)d_out;
    float* out_w = out_a + (size_t)BB * SS * DF;  // w follows a

    // pre-round K/V into compacted tf32 scratch
    round_kv_kernel<<<(KVN / 4) / NT, NT>>>(k, v);

    cudaFuncSetAttribute(attn_mma_kernel,
                         cudaFuncAttributeMaxDynamicSharedMemorySize, SM_TOTAL);
    dim3 grid(SS / BQ, HH, BB);   // (64, 16, 4) = 4096 CTAs
    attn_mma_kernel<<<grid, NT, SM_TOTAL>>>(q, out_a, out_w);
}

// round 10
// speedup vs baseline: 1.3243x; 1.3243x over previous
#include <cuda_runtime.h>
#include <cstdint>

// Problem constants
#define BB 4
#define SS 4096
#define DF 1024
#define HH 16
#define HD 64
#define SK 1024          // SS / STRIDE
#define STRIDE 4
#define BQ 128           // q rows per CTA
#define BK 64            // k cols per block
#define NBLK 16
#define NT 256
#define NQB 32           // q-blocks per (b,h)

// fragment-major, tf32-pre-rounded scratch
// K': per (b,h,kblk): [j(8)][tt(8)][lane(32)][2]    = 4096 floats
// V': per (b,h,kblk): [jt(8)][t(8)][lane(32)][2]    = 4096 floats
// Q': per (b,h,qblk): [j(8)][mg(8)][lane(32)][4]    = 8192 floats
__device__ float g_kf[BB * HH * NBLK * 4096];
__device__ float g_vf[BB * HH * NBLK * 4096];
__device__ float g_qf[BB * HH * NQB * 8192];

#define STG_FLOATS 4096        // one 64x64 stage
#define SM_TOTAL   65536       // 4 stages

__device__ __forceinline__ uint32_t smem_u32(const void* p) {
    uint32_t a;
    asm("{ .reg .u64 t; cvta.to.shared.u64 t, %1; cvt.u32.u64 %0, t; }" : "=r"(a) : "l"(p));
    return a;
}
#define CP_ASYNC16(sa, gp) \
    asm volatile("cp.async.cg.shared.global [%0], [%1], 16;" :: "r"(sa), "l"(gp) : "memory")
#define CP_COMMIT() asm volatile("cp.async.commit_group;" ::: "memory")
#define CP_WAIT(N)  asm volatile("cp.async.wait_group %0;" :: "n"(N) : "memory")

__device__ __forceinline__ void mma_tf32(float c[4], const float a[4],
                                         float b0, float b1) {
    asm volatile(
        "mma.sync.aligned.m16n8k8.row.col.f32.tf32.tf32.f32 "
        "{%0,%1,%2,%3}, {%4,%5,%6,%7}, {%8,%9}, {%0,%1,%2,%3};"
        : "+f"(c[0]), "+f"(c[1]), "+f"(c[2]), "+f"(c[3])
        : "r"(__float_as_uint(a[0])), "r"(__float_as_uint(a[1])),
          "r"(__float_as_uint(a[2])), "r"(__float_as_uint(a[3])),
          "r"(__float_as_uint(b0)), "r"(__float_as_uint(b1)));
}
__device__ __forceinline__ float tf32_rn(float x) {
    return __uint_as_float((__float_as_uint(x) + 0x1000u) & 0xFFFFE000u);
}
__device__ __forceinline__ float ex2f(float x) {
    float y;
    asm("ex2.approx.f32 %0, %1;" : "=f"(y) : "f"(x));
    return y;
}

// ---- pre-kernels: gather into fragment-major tf32 scratch ----
// K': b0 = K[kblk*64 + tt*8 + gid][j*8 + 2gc], b1 = col+1  (strided rows)
__global__ __launch_bounds__(NT)
void shuffle_k_kernel(const float* __restrict__ gk)
{
    int id = blockIdx.x * NT + threadIdx.x;
    int lane = id & 31, tt = (id >> 5) & 7, j = (id >> 8) & 7;
    int kblk = (id >> 11) & 15, bh = id >> 15;
    int gid = lane >> 2, gc = lane & 3;
    int s = (kblk * 64 + tt * 8 + gid) * STRIDE;
    int c = (bh & 15) * HD + j * 8 + 2 * gc;
    const float* src = gk + ((size_t)(bh >> 4) * SS + s) * DF + c;
    *(float2*)&g_kf[(size_t)id * 2] = make_float2(tf32_rn(src[0]), tf32_rn(src[1]));
}
// V': b0 = V[kblk*64 + jt*8 + 2gc][t*8 + gid], b1 = next key row
__global__ __launch_bounds__(NT)
void shuffle_v_kernel(const float* __restrict__ gv)
{
    int id = blockIdx.x * NT + threadIdx.x;
    int lane = id & 31, t = (id >> 5) & 7, jt = (id >> 8) & 7;
    int kblk = (id >> 11) & 15, bh = id >> 15;
    int gid = lane >> 2, gc = lane & 3;
    int s = (kblk * 64 + jt * 8 + 2 * gc) * STRIDE;
    int c = (bh & 15) * HD + t * 8 + gid;
    const float* src = gv + ((size_t)(bh >> 4) * SS + s) * DF + c;
    *(float2*)&g_vf[(size_t)id * 2] =
        make_float2(tf32_rn(src[0]), tf32_rn(src[(size_t)STRIDE * DF]));
}
// Q': a-frag {Q[r][c], Q[r+8][c], Q[r][c+1], Q[r+8][c+1]} * 0.125*log2(e), rn
__global__ __launch_bounds__(NT)
void shuffle_q_kernel(const float* __restrict__ gq)
{
    const float SCL = 0.125f * 1.44269504088896341f;
    int id = blockIdx.x * NT + threadIdx.x;
    int lane = id & 31, mg = (id >> 5) & 7, j = (id >> 8) & 7;
    int qblk = (id >> 11) & 31, bh = id >> 16;
    int gid = lane >> 2, gc = lane & 3;
    int r = qblk * BQ + mg * 16 + gid;
    int c = (bh & 15) * HD + j * 8 + 2 * gc;
    const float* src = gq + ((size_t)(bh >> 4) * SS + r) * DF + c;
    float4 o;
    o.x = tf32_rn(src[0] * SCL);
    o.y = tf32_rn(src[(size_t)8 * DF] * SCL);
    o.z = tf32_rn(src[1] * SCL);
    o.w = tf32_rn(src[(size_t)8 * DF + 1] * SCL);
    *(float4*)&g_qf[(size_t)id * 4] = o;
}

__global__ __launch_bounds__(NT, 2)
void attn_mma_kernel(float* __restrict__ out_a, float* __restrict__ out_w)
{
    extern __shared__ float sm[];
    const uint32_t smb = smem_u32(sm);

    const int tid = threadIdx.x, lane = tid & 31, warp = tid >> 5;
    const int gid = lane >> 2, gc = lane & 3;
    const int b = blockIdx.z, h = blockIdx.y, qblk = blockIdx.x;
    const int bh = b * HH + h;
    const int r0 = warp * 16 + gid;                  // warp owns q rows warp*16..+15

    const float* kf = g_kf + (size_t)bh * NBLK * 4096;
    const float* vf = g_vf + (size_t)bh * NBLK * 4096;
    const float* qf = g_qf + ((size_t)bh * NQB + qblk) * 8192;

    // ---- pass1 pre-issue: K blocks 0..2 into stages 0..2 ----
    #pragma unroll
    for (int p = 0; p < 3; p++) {
        const uint32_t st = smb + p * (STG_FLOATS * 4);
        const float* src = kf + p * STG_FLOATS;
        #pragma unroll
        for (int i = 0; i < 4; i++) {
            int cix = tid + i * NT;
            CP_ASYNC16(st + cix * 16, src + cix * 4);
        }
        CP_COMMIT();
    }

    // ---- Q fragments -> registers (coalesced LDG.128, 512B per warp) ----
    float Qf[8][4];
    #pragma unroll
    for (int j = 0; j < 8; j++) {
        float4 qv = *(const float4*)&qf[(size_t)((j * 8 + warp) * 32 + lane) * 4];
        Qf[j][0] = qv.x; Qf[j][1] = qv.y; Qf[j][2] = qv.z; Qf[j][3] = qv.w;
    }

    float rs0 = 0.f, rs1 = 0.f;

    // ================= PASS 1: row sums (K ring over 4 stages) =================
    for (int blk = 0; blk < NBLK; blk++) {
        if      (blk < NBLK - 2)  CP_WAIT(2);
        else if (blk == NBLK - 2) CP_WAIT(1);
        else                      CP_WAIT(0);
        __syncthreads();

        if (blk + 3 < NBLK) {
            const uint32_t st = smb + ((blk + 3) & 3) * (STG_FLOATS * 4);
            const float* src = kf + (blk + 3) * STG_FLOATS;
            #pragma unroll
            for (int i = 0; i < 4; i++) {
                int cix = tid + i * NT;
                CP_ASYNC16(st + cix * 16, src + cix * 4);
            }
            CP_COMMIT();
        }

        const float* kb = sm + (blk & 3) * STG_FLOATS;

        float S[8][4];
        #pragma unroll
        for (int t = 0; t < 8; t++) {
            S[t][0] = 0.f; S[t][1] = 0.f; S[t][2] = 0.f; S[t][3] = 0.f;
        }
        #pragma unroll
        for (int j = 0; j < 8; j++) {
            #pragma unroll
            for (int t = 0; t < 8; t++) {
                float2 bk = *(const float2*)&kb[(j * 8 + t) * 64 + lane * 2];
                mma_tf32(S[t], Qf[j], bk.x, bk.y);
            }
        }
        #pragma unroll
        for (int t = 0; t < 8; t++) {
            rs0 += ex2f(S[t][0]) + ex2f(S[t][1]);
            rs1 += ex2f(S[t][2]) + ex2f(S[t][3]);
        }
    }

    // quad reduce -> per-row inverses (warp-local, all 4 lanes get totals)
    rs0 += __shfl_xor_sync(0xFFFFFFFFu, rs0, 1);
    rs0 += __shfl_xor_sync(0xFFFFFFFFu, rs0, 2);
    rs1 += __shfl_xor_sync(0xFFFFFFFFu, rs1, 1);
    rs1 += __shfl_xor_sync(0xFFFFFFFFu, rs1, 2);
    const float inv0 = 1.0f / rs0, inv1 = 1.0f / rs1;

    // ---- pass2 pre-issue: K(0)->stage0, V(0)->stage2 (one group) ----
    {
        #pragma unroll
        for (int i = 0; i < 4; i++) {
            int cix = tid + i * NT;
            CP_ASYNC16(smb + cix * 16,                        kf + cix * 4);
            CP_ASYNC16(smb + 2 * (STG_FLOATS * 4) + cix * 16, vf + cix * 4);
        }
        CP_COMMIT();
    }

    float Acc[8][4];
    #pragma unroll
    for (int t = 0; t < 8; t++) {
        Acc[t][0] = 0.f; Acc[t][1] = 0.f; Acc[t][2] = 0.f; Acc[t][3] = 0.f;
    }

    // ================= PASS 2: normalized w + PV =================
    for (int blk = 0; blk < NBLK; blk++) {
        CP_WAIT(0);
        __syncthreads();

        if (blk + 1 < NBLK) {
            const uint32_t ks_ = smb + ((blk + 1) & 1) * (STG_FLOATS * 4);
            const uint32_t vs_ = ks_ + 2 * (STG_FLOATS * 4);
            const float* ksrc = kf + (blk + 1) * STG_FLOATS;
            const float* vsrc = vf + (blk + 1) * STG_FLOATS;
            #pragma unroll
            for (int i = 0; i < 4; i++) {
                int cix = tid + i * NT;
                CP_ASYNC16(ks_ + cix * 16, ksrc + cix * 4);
                CP_ASYNC16(vs_ + cix * 16, vsrc + cix * 4);
            }
            CP_COMMIT();
        }

        const float* kb = sm + (blk & 1) * STG_FLOATS;
        const float* vb = sm + (2 + (blk & 1)) * STG_FLOATS;

        // ---- S = Q * K^T  (identical op order to pass 1 -> same bits) ----
        float S[8][4];
        #pragma unroll
        for (int t = 0; t < 8; t++) {
            S[t][0] = 0.f; S[t][1] = 0.f; S[t][2] = 0.f; S[t][3] = 0.f;
        }
        #pragma unroll
        for (int j = 0; j < 8; j++) {
            #pragma unroll
            for (int t = 0; t < 8; t++) {
                float2 bk = *(const float2*)&kb[(j * 8 + t) * 64 + lane * 2];
                mma_tf32(S[t], Qf[j], bk.x, bk.y);
            }
        }

        // ---- normalized w -> gmem; S becomes normalized P in regs ----
        float* wr0 = out_w + ((size_t)bh * SS + qblk * BQ + r0) * SK + blk * BK;
        float* wr1 = wr0 + (size_t)8 * SK;
        #pragma unroll
        for (int t = 0; t < 8; t++) {
            float p0 = ex2f(S[t][0]) * inv0, p1 = ex2f(S[t][1]) * inv0;
            float p2 = ex2f(S[t][2]) * inv1, p3 = ex2f(S[t][3]) * inv1;
            int col = t * 8 + 2 * gc;
            *(float2*)&wr0[col] = make_float2(p0, p1);
            *(float2*)&wr1[col] = make_float2(p2, p3);
            S[t][0] = p0; S[t][1] = p1; S[t][2] = p2; S[t][3] = p3;
        }

        // ---- Acc += P * V  (C->A feed; V' fragment-major float2) ----
        #pragma unroll
        for (int jt = 0; jt < 8; jt++) {
            float ap[4];
            ap[0] = S[jt][0]; ap[1] = S[jt][2];
            ap[2] = S[jt][1]; ap[3] = S[jt][3];
            #pragma unroll
            for (int t = 0; t < 8; t++) {
                float2 bv = *(const float2*)&vb[(jt * 8 + t) * 64 + lane * 2];
                mma_tf32(Acc[t], ap, bv.x, bv.y);
            }
        }
    }

    // ---- a: already normalized ----
    {
        float* ar0 = out_a + ((size_t)(b * SS + qblk * BQ + r0)) * DF + h * HD;
        float* ar1 = ar0 + (size_t)8 * DF;
        #pragma unroll
        for (int t = 0; t < 8; t++) {
            int col = t * 8 + 2 * gc;
            *(float2*)&ar0[col] = make_float2(Acc[t][0], Acc[t][1]);
            *(float2*)&ar1[col] = make_float2(Acc[t][2], Acc[t][3]);
        }
    }
}

extern "C" void kernel_launch(void* const* d_in, const int* in_sizes, int n_in,
                              void* d_out, int out_size)
{
    (void)in_sizes; (void)n_in; (void)out_size;
    const float* q = (const float*)d_in[0];
    const float* k = (const float*)d_in[1];
    const float* v = (const float*)d_in[2];

    float* out_a = (float*)d_out;
    float* out_w = out_a + (size_t)BB * SS * DF;  // w follows a

    shuffle_k_kernel<<<(BB * HH * NBLK * 2048) / NT, NT>>>(k);
    shuffle_v_kernel<<<(BB * HH * NBLK * 2048) / NT, NT>>>(v);
    shuffle_q_kernel<<<(BB * HH * NQB * 2048) / NT, NT>>>(q);

    cudaFuncSetAttribute(attn_mma_kernel,
                         cudaFuncAttributeMaxDynamicSharedMemorySize, SM_TOTAL);
    dim3 grid(NQB, HH, BB);   // (32, 16, 4) = 2048 CTAs
    attn_mma_kernel<<<grid, NT, SM_TOTAL>>>(out_a, out_w);
}